// round 15
// baseline (speedup 1.0000x reference)
#include <cuda_runtime.h>
#include <cstdint>

#define CIN  10
#define C    64
#define SMAX 30001
#define EPS  1e-3f
#define FULLMASK 0xffffffffu

typedef unsigned long long u64;

// ---------------- parameter staging (read by k_pipe into shared) ----------------
struct Params {
    u64   Wfp[32 * CIN];   // BN-folded linear weights, channel-pair packed
    u64   biasp[32];
    u64   dwp[32];
    float xg[C];
};
__device__ Params g_stage;

// ---------------- device scratch ----------------
__device__ float g_m1[CIN];
__device__ float g_m2[55];
__device__ float g_Wf[C * CIN];
__device__ float g_bias[C];
__device__ float g_gsum[C];
__device__ int   g_segstart[SMAX];
__device__ unsigned g_syncA;     // last-block tickets
__device__ unsigned g_syncB;
// per-pillar partials, 2 slots (pillar-start subtile / spill subtile)
__device__ float g_pmax[(size_t)2 * SMAX * C];
__device__ float g_psum[(size_t)2 * SMAX * C];

// ---------------- packed f32x2 / bf16 helpers ----------------
__device__ __forceinline__ u64 pack2(float lo, float hi) {
    u64 r; asm("mov.b64 %0, {%1, %2};" : "=l"(r) : "f"(lo), "f"(hi)); return r;
}
__device__ __forceinline__ void unpack2(u64 v, float& lo, float& hi) {
    asm("mov.b64 {%0, %1}, %2;" : "=f"(lo), "=f"(hi) : "l"(v));
}
__device__ __forceinline__ u64 fma2(u64 a, u64 b, u64 c) {
    u64 d; asm("fma.rn.f32x2 %0, %1, %2, %3;" : "=l"(d) : "l"(a), "l"(b), "l"(c)); return d;
}
__device__ __forceinline__ u64 mul2(u64 a, u64 b) {
    u64 d; asm("mul.rn.f32x2 %0, %1, %2;" : "=l"(d) : "l"(a), "l"(b)); return d;
}
// pack two f32 -> bf16x2 (hi goes to upper half)
__device__ __forceinline__ unsigned int cvt2bf(float hi, float lo) {
    unsigned int r;
    asm("cvt.rn.satfinite.bf16x2.f32 %0, %1, %2;" : "=r"(r) : "f"(hi), "f"(lo));
    return r;
}

__device__ __forceinline__ float sigmoidf_fast(float z) {
    return __fdividef(1.0f, 1.0f + __expf(-z));
}
__device__ __forceinline__ float warp_sum(float v) {
#pragma unroll
    for (int o = 16; o > 0; o >>= 1) v += __shfl_down_sync(FULLMASK, v, o);
    return v;
}

// ---------------- K1: zero accumulators + segment boundaries ----------------
__global__ void k_bounds(const int* __restrict__ unq, int n, int s_count) {
    if (blockIdx.x == 0) {
        int t = threadIdx.x;
        if (t < CIN) g_m1[t] = 0.0f;
        if (t < 55)  g_m2[t] = 0.0f;
        if (t < C)   g_gsum[t] = 0.0f;
        if (t == 0) { g_syncA = 0u; g_syncB = 0u; }
    }
    int i = blockIdx.x * blockDim.x + threadIdx.x;
    if (i >= n) return;
    int cur = unq[i];
    if (i == 0) {
        for (int t = 0; t <= cur; t++) g_segstart[t] = 0;
    } else {
        int prev = unq[i - 1];
        for (int t = prev + 1; t <= cur; t++) g_segstart[t] = i;
    }
    if (i == n - 1) {
        for (int t = cur + 1; t <= s_count; t++) g_segstart[t] = n;
    }
}

// ---------------- K2: moments + (last block) BN fold + param staging ----------------
__global__ __launch_bounds__(256) void k_moments_fold(
        const float* __restrict__ inp,
        const float* __restrict__ W, const float* __restrict__ gamma,
        const float* __restrict__ beta, const float* __restrict__ dw1, int n) {
    float a1[CIN];
    float a2[55];
#pragma unroll
    for (int k = 0; k < CIN; k++) a1[k] = 0.0f;
#pragma unroll
    for (int k = 0; k < 55; k++) a2[k] = 0.0f;

    int stride = gridDim.x * blockDim.x;
    for (int i = blockIdx.x * blockDim.x + threadIdx.x; i < n; i += stride) {
        const float* row = inp + (size_t)i * CIN;
        float v[CIN];
#pragma unroll
        for (int k = 0; k < CIN; k++) v[k] = __ldg(row + k);
        int t = 0;
#pragma unroll
        for (int j = 0; j < CIN; j++) {
            a1[j] += v[j];
#pragma unroll
            for (int k = j; k < CIN; k++) { a2[t] += v[j] * v[k]; t++; }
        }
    }

    int lane = threadIdx.x & 31;
#pragma unroll
    for (int j = 0; j < CIN; j++) {
        float r = warp_sum(a1[j]);
        if (lane == 0) atomicAdd(&g_m1[j], r);
    }
#pragma unroll
    for (int t = 0; t < 55; t++) {
        float r = warp_sum(a2[t]);
        if (lane == 0) atomicAdd(&g_m2[t], r);
    }

    // ---- last-block: BN fold + packed-param staging ----
    __threadfence();
    __shared__ unsigned s_ticket;
    if (threadIdx.x == 0) s_ticket = atomicAdd(&g_syncA, 1u);
    __syncthreads();
    if (s_ticket != gridDim.x - 1) return;

    int c = threadIdx.x;
    if (c < C) {
        float invn = 1.0f / (float)n;
        float wr[CIN];
#pragma unroll
        for (int k = 0; k < CIN; k++) wr[k] = W[c * CIN + k];

        float mu = 0.0f;
#pragma unroll
        for (int k = 0; k < CIN; k++) mu += wr[k] * g_m1[k];
        mu *= invn;

        float ex2 = 0.0f;
        int t = 0;
#pragma unroll
        for (int j = 0; j < CIN; j++) {
#pragma unroll
            for (int k = j; k < CIN; k++) {
                float f = wr[j] * wr[k] * g_m2[t];
                ex2 += (k == j) ? f : 2.0f * f;
                t++;
            }
        }
        ex2 *= invn;
        float var = ex2 - mu * mu;
        float alpha = gamma[c] * rsqrtf(var + EPS);
        g_bias[c] = beta[c] - mu * alpha;
#pragma unroll
        for (int k = 0; k < CIN; k++) g_Wf[c * CIN + k] = alpha * wr[k];
    }
    __syncthreads();
    if (c < 32) {
#pragma unroll
        for (int k = 0; k < CIN; k++)
            g_stage.Wfp[c * CIN + k] = pack2(g_Wf[(2 * c) * CIN + k],
                                             g_Wf[(2 * c + 1) * CIN + k]);
        g_stage.biasp[c] = pack2(g_bias[2 * c], g_bias[2 * c + 1]);
        g_stage.dwp[c]   = pack2(dw1[2 * c], dw1[2 * c + 1]);
    }
}

// ---------------- K3: gpass + (last block) global branch xg ----------------
#define GP_TILE 256
__global__ __launch_bounds__(256) void k_gpass_xg(
        const float* __restrict__ inp,
        const float* __restrict__ dw2, const float* __restrict__ pw2, int n) {
    __shared__ __align__(16) float s_v[GP_TILE * 12];
    __shared__ float s_acc[C];

    int t = threadIdx.x;
    int c = t & 63, g = t >> 6;

    float w[CIN];
#pragma unroll
    for (int k = 0; k < CIN; k++) w[k] = g_Wf[c * CIN + k];
    float b = g_bias[c];
    if (t < C) s_acc[t] = 0.0f;

    float acc = 0.0f;
    for (int base = blockIdx.x * GP_TILE; base < n; base += gridDim.x * GP_TILE) {
        int cnt = n - base; if (cnt > GP_TILE) cnt = GP_TILE;
        __syncthreads();
        for (int i = t; i < cnt * CIN; i += 256) {
            int r = i / CIN, k = i - r * CIN;
            s_v[r * 12 + k] = inp[(size_t)base * CIN + i];
        }
        __syncthreads();
        int p0 = g * 64, p1 = p0 + 64; if (p1 > cnt) p1 = cnt;
        for (int p = p0; p < p1; p++) {
            const float* vr = s_v + p * 12;
            float4 va = *reinterpret_cast<const float4*>(vr);
            float4 vb = *reinterpret_cast<const float4*>(vr + 4);
            float2 vc = *reinterpret_cast<const float2*>(vr + 8);
            float x = b;
            x += w[0] * va.x; x += w[1] * va.y; x += w[2] * va.z; x += w[3] * va.w;
            x += w[4] * vb.x; x += w[5] * vb.y; x += w[6] * vb.z; x += w[7] * vb.w;
            x += w[8] * vc.x; x += w[9] * vc.y;
            acc += fmaxf(x, 0.0f);
        }
    }
    atomicAdd(&s_acc[c], acc);
    __syncthreads();
    if (t < C) atomicAdd(&g_gsum[t], s_acc[t]);

    // ---- last-block: xg = pw2 @ relu(dw2 * mean(x)) ----
    __threadfence();
    __shared__ unsigned s_ticket;
    if (t == 0) s_ticket = atomicAdd(&g_syncB, 1u);
    __syncthreads();
    if (s_ticket != gridDim.x - 1) return;

    __shared__ float tt[C];
    if (t < C) tt[t] = fmaxf(dw2[t] * (g_gsum[t] / (float)n), 0.0f);
    __syncthreads();
    if (t < C) {
        float a = 0.0f;
#pragma unroll
        for (int k = 0; k < C; k++) a += pw2[t * C + k] * tt[k];
        g_stage.xg[t] = a;
    }
}

// ---------------- K4: fused pipeline, bf16 mma.sync phase B ----------------
// dynamic shared layout (bytes):
//   xT   [64][130] f32      @ 0      (33280)  x then xi, transposed [ch][pt]
//   swA  [128 pt][144B]     @ 33280  (18432)  sw bf16, row = point, 64 k + pad
//   pwB  [64 n][144B]       @ 51712  (9216)   pw1 bf16, row = out-ch, 64 k + pad
//   Wfp  [32*10]   u64      @ 60928  (2560)
//   bp   [32]      u64      @ 63488  (256)
//   dwp  [32]      u64      @ 63744  (256)
//   xg   [64]      f32      @ 64000  (256)
//   s_u  [128]     int      @ 64256  (512)
#define XT_S    130
#define SWA_STRIDE_B 144
#define PWB_STRIDE_B 144
#define OFF_SWA 33280
#define OFF_PWB 51712
#define OFF_WFP 60928
#define OFF_BP  63488
#define OFF_DWP 63744
#define OFF_XG  64000
#define OFF_U   64256
#define PIPE_SMEM 64768

__global__ __launch_bounds__(128, 3) void k_pipe(const float* __restrict__ inp,
                                                 const float* __restrict__ pw1,
                                                 const int* __restrict__ unq,
                                                 int n) {
    extern __shared__ __align__(16) char dsm[];
    float* xT   = reinterpret_cast<float*>(dsm);
    unsigned int* swA32 = reinterpret_cast<unsigned int*>(dsm + OFF_SWA);
    unsigned int* pwB32 = reinterpret_cast<unsigned int*>(dsm + OFF_PWB);
    const ulonglong2* Wfp2 = reinterpret_cast<const ulonglong2*>(dsm + OFF_WFP);
    u64*   wfpw = reinterpret_cast<u64*>(dsm + OFF_WFP);
    u64*   bp   = reinterpret_cast<u64*>(dsm + OFF_BP);
    u64*   dwp  = reinterpret_cast<u64*>(dsm + OFF_DWP);
    float* s_xg = reinterpret_cast<float*>(dsm + OFF_XG);
    int*   s_u  = reinterpret_cast<int*>(dsm + OFF_U);

    int li = threadIdx.x;
    int base = blockIdx.x * 128;
    int cnt = n - base; if (cnt > 128) cnt = 128;
    bool havept = li < cnt;

    // ---- early loads: issue point-row + unq LDGs first so DRAM latency
    //      overlaps the staging loops and the barrier ----
    float vin[CIN];
    int myu = 0;
    if (havept) {
        const float* row = inp + (size_t)(base + li) * CIN;
#pragma unroll
        for (int k = 0; k < CIN; k++) vin[k] = __ldg(row + k);
        myu = __ldg(unq + base + li);
    }

    // staging: pw1 [c][k] f32 -> pwB bf16 rows (n-major, k contiguous)
    for (int idx = li; idx < 2048; idx += 128) {
        int c = idx >> 5, kp = idx & 31;
        float2 v = __ldg(reinterpret_cast<const float2*>(pw1 + c * C + 2 * kp));
        pwB32[c * 36 + kp] = cvt2bf(v.y, v.x);
    }
    for (int t = li; t < 32 * CIN; t += 128) wfpw[t] = g_stage.Wfp[t];
    if (li < 32) { bp[li] = g_stage.biasp[li]; dwp[li] = g_stage.dwp[li]; }
    if (li < C) s_xg[li] = g_stage.xg[li];
    if (havept) s_u[li] = myu;
    __syncthreads();

    // ---- phase A: per-point folded linear + relu + swish (x -> xT, sw -> swA bf16) ----
    if (havept) {
        u64 vd[CIN];
#pragma unroll
        for (int k = 0; k < CIN; k++) vd[k] = pack2(vin[k], vin[k]);
#pragma unroll
        for (int cp = 0; cp < 32; cp++) {
            ulonglong2 wA = Wfp2[cp * 5 + 0];
            ulonglong2 wB = Wfp2[cp * 5 + 1];
            ulonglong2 wC = Wfp2[cp * 5 + 2];
            ulonglong2 wD = Wfp2[cp * 5 + 3];
            ulonglong2 wE = Wfp2[cp * 5 + 4];
            u64 a = bp[cp];
            a = fma2(wA.x, vd[0], a); a = fma2(wA.y, vd[1], a);
            a = fma2(wB.x, vd[2], a); a = fma2(wB.y, vd[3], a);
            a = fma2(wC.x, vd[4], a); a = fma2(wC.y, vd[5], a);
            a = fma2(wD.x, vd[6], a); a = fma2(wD.y, vd[7], a);
            a = fma2(wE.x, vd[8], a); a = fma2(wE.y, vd[9], a);
            float lo, hi; unpack2(a, lo, hi);
            lo = fmaxf(lo, 0.0f); hi = fmaxf(hi, 0.0f);
            xT[(2 * cp) * XT_S + li]     = lo;
            xT[(2 * cp + 1) * XT_S + li] = hi;
            u64 sp = mul2(pack2(lo, hi), dwp[cp]);
            float sa, sb; unpack2(sp, sa, sb);
            float swa = sa * sigmoidf_fast(sa);
            float swb = sb * sigmoidf_fast(sb);
            swA32[li * 36 + cp] = cvt2bf(swb, swa);   // lo16 = k even, hi16 = k odd
        }
    } else {
#pragma unroll
        for (int c = 0; c < C; c++) xT[c * XT_S + li] = 0.0f;
#pragma unroll
        for (int cp = 0; cp < 32; cp++) swA32[li * 36 + cp] = 0u;
    }
    __syncthreads();

    // ---- phase B: tensor-core GEMM xl[p][c] = sum_k sw[p][k] * pwB[c][k] ----
    {
        int w = li >> 5, lane = li & 31;
        int mbase = w * 32;

        unsigned swA_base = (unsigned)__cvta_generic_to_shared(dsm + OFF_SWA);
        unsigned pwB_base = (unsigned)__cvta_generic_to_shared(dsm + OFF_PWB);

        float acc[2][8][4];
#pragma unroll
        for (int mt = 0; mt < 2; mt++)
#pragma unroll
            for (int j = 0; j < 8; j++)
#pragma unroll
                for (int r = 0; r < 4; r++) acc[mt][j][r] = 0.0f;

#pragma unroll
        for (int t = 0; t < 4; t++) {
            unsigned int a[2][4];
#pragma unroll
            for (int mt = 0; mt < 2; mt++) {
                unsigned addrA = swA_base
                    + (mbase + mt * 16 + (lane & 15)) * SWA_STRIDE_B
                    + (lane >> 4) * 16 + t * 32;
                asm volatile(
                    "ldmatrix.sync.aligned.m8n8.x4.shared.b16 {%0,%1,%2,%3}, [%4];"
                    : "=r"(a[mt][0]), "=r"(a[mt][1]), "=r"(a[mt][2]), "=r"(a[mt][3])
                    : "r"(addrA));
            }
#pragma unroll
            for (int j = 0; j < 8; j++) {
                unsigned int b0, b1;
                unsigned addrB = pwB_base
                    + (8 * j + (lane & 7)) * PWB_STRIDE_B
                    + ((lane >> 3) & 1) * 16 + t * 32;
                asm volatile(
                    "ldmatrix.sync.aligned.m8n8.x2.shared.b16 {%0,%1}, [%2];"
                    : "=r"(b0), "=r"(b1) : "r"(addrB));
#pragma unroll
                for (int mt = 0; mt < 2; mt++) {
                    asm volatile(
                        "mma.sync.aligned.m16n8k16.row.col.f32.bf16.bf16.f32 "
                        "{%0,%1,%2,%3}, {%4,%5,%6,%7}, {%8,%9}, {%0,%1,%2,%3};"
                        : "+f"(acc[mt][j][0]), "+f"(acc[mt][j][1]),
                          "+f"(acc[mt][j][2]), "+f"(acc[mt][j][3])
                        : "r"(a[mt][0]), "r"(a[mt][1]), "r"(a[mt][2]), "r"(a[mt][3]),
                          "r"(b0), "r"(b1));
                }
            }
        }

        // epilogue: wei = sigmoid(xl + xg); xi = x*(1+wei) into xT in place
#pragma unroll
        for (int mt = 0; mt < 2; mt++) {
            int prow = mbase + mt * 16 + (lane >> 2);
#pragma unroll
            for (int j = 0; j < 8; j++) {
                int c0 = 8 * j + 2 * (lane & 3);
                float xg0 = s_xg[c0], xg1 = s_xg[c0 + 1];
#pragma unroll
                for (int h = 0; h < 2; h++) {
                    int p = prow + 8 * h;
                    float w0 = 1.0f + sigmoidf_fast(acc[mt][j][2 * h]     + xg0);
                    float w1 = 1.0f + sigmoidf_fast(acc[mt][j][2 * h + 1] + xg1);
                    xT[c0 * XT_S + p]       *= w0;
                    xT[(c0 + 1) * XT_S + p] *= w1;
                }
            }
        }
    }
    __syncthreads();

    // ---- phase C: per-pillar partial (max,sum) per 64-pt subtile -> 2-slot scratch ----
    {
        int h = li >> 6, c = li & 63;
        int p = h * 64, pend = p + 64; if (pend > cnt) pend = cnt;
        if (p < pend) {
            int mytile = (base >> 6) + h;
            int cur = s_u[p];
            float v = xT[c * XT_S + p];
            float mx = v, sm = v;
            for (p++; p < pend; p++) {
                int u = s_u[p];
                float w = xT[c * XT_S + p];
                if (u != cur) {
                    size_t slot = ((g_segstart[cur] >> 6) == mytile) ? 0 : 1;
                    size_t idx = slot * ((size_t)SMAX * C) + (size_t)cur * C + c;
                    g_pmax[idx] = mx;
                    g_psum[idx] = sm;
                    cur = u; mx = w; sm = w;
                } else {
                    mx = fmaxf(mx, w); sm += w;
                }
            }
            size_t slot = ((g_segstart[cur] >> 6) == mytile) ? 0 : 1;
            size_t idx = slot * ((size_t)SMAX * C) + (size_t)cur * C + c;
            g_pmax[idx] = mx;
            g_psum[idx] = sm;
        }
    }
}

// ---------------- K5: combine per-pillar partials -> out ----------------
__global__ __launch_bounds__(256) void k_combine(float* __restrict__ out, int s_count) {
    int s = blockIdx.x * 8 + (threadIdx.x >> 5);
    int lane = threadIdx.x & 31;
    if (s >= s_count) return;
    int p0 = g_segstart[s], p1 = g_segstart[s + 1];
    size_t i0 = (size_t)s * C + 2 * lane;
    if (p1 <= p0) {
        out[i0] = 0.0f; out[i0 + 1] = 0.0f;
        return;
    }
    float2 m = *reinterpret_cast<const float2*>(g_pmax + i0);
    float2 q = *reinterpret_cast<const float2*>(g_psum + i0);
    if (((p1 - 1) >> 6) > (p0 >> 6)) {
        size_t i1 = (size_t)SMAX * C + i0;
        float2 m1 = *reinterpret_cast<const float2*>(g_pmax + i1);
        float2 q1 = *reinterpret_cast<const float2*>(g_psum + i1);
        m.x = fmaxf(m.x, m1.x); m.y = fmaxf(m.y, m1.y);
        q.x += q1.x; q.y += q1.y;
    }
    *reinterpret_cast<float2*>(out + i0) = make_float2(m.x + q.x, m.y + q.y);
}

// ---------------- launch ----------------
extern "C" void kernel_launch(void* const* d_in, const int* in_sizes, int n_in,
                              void* d_out, int out_size) {
    const float* inp   = (const float*)d_in[0];
    const int*   unq   = (const int*)d_in[1];
    const float* W     = (const float*)d_in[2];
    const float* gamma = (const float*)d_in[3];
    const float* beta  = (const float*)d_in[4];
    const float* dw1   = (const float*)d_in[5];
    const float* pw1   = (const float*)d_in[6];
    const float* dw2   = (const float*)d_in[7];
    const float* pw2   = (const float*)d_in[8];
    float* out = (float*)d_out;

    int n = in_sizes[0] / CIN;     // 1,000,000
    int s = out_size / C;          // 30,000

    static bool attr_done = false;
    if (!attr_done) {
        cudaFuncSetAttribute(k_pipe, cudaFuncAttributeMaxDynamicSharedMemorySize,
                             PIPE_SMEM);
        attr_done = true;
    }

    k_bounds<<<(n + 255) / 256, 256>>>(unq, n, s);                    // my launch 1
    k_moments_fold<<<592, 256>>>(inp, W, gamma, beta, dw1, n);        // my launch 2
    k_gpass_xg<<<592, 256>>>(inp, dw2, pw2, n);                       // my launch 3
    k_pipe<<<(n + 127) / 128, 128, PIPE_SMEM>>>(inp, pw1, unq, n);    // my launch 4
    k_combine<<<(s + 7) / 8, 256>>>(out, s);                          // my launch 5
}

// round 16
// speedup vs baseline: 1.0750x; 1.0750x over previous
#include <cuda_runtime.h>
#include <cstdint>

#define CIN  10
#define C    64
#define SMAX 30001
#define EPS  1e-3f
#define FULLMASK 0xffffffffu

typedef unsigned long long u64;

// ---------------- parameter staging (read by k_pipe into shared) ----------------
struct Params {
    u64   Wfp[32 * CIN];   // BN-folded linear weights, channel-pair packed
    u64   biasp[32];
    u64   dwp[32];
    float xg[C];
};
__device__ Params g_stage;

// ---------------- device scratch ----------------
__device__ float g_m1[CIN];
__device__ float g_m2[55];
__device__ float g_Wf[C * CIN];
__device__ float g_bias[C];
__device__ float g_gsum[C];
__device__ int   g_segstart[SMAX];
__device__ unsigned g_syncA;     // last-block tickets
__device__ unsigned g_syncB;
__device__ unsigned g_pwB[2048]; // pw1 as bf16x2, [c][kp] (kp = k/2)
// per-pillar partials, 2 slots (pillar-start subtile / spill subtile)
__device__ float g_pmax[(size_t)2 * SMAX * C];
__device__ float g_psum[(size_t)2 * SMAX * C];

// ---------------- packed f32x2 / bf16 helpers ----------------
__device__ __forceinline__ u64 pack2(float lo, float hi) {
    u64 r; asm("mov.b64 %0, {%1, %2};" : "=l"(r) : "f"(lo), "f"(hi)); return r;
}
__device__ __forceinline__ void unpack2(u64 v, float& lo, float& hi) {
    asm("mov.b64 {%0, %1}, %2;" : "=f"(lo), "=f"(hi) : "l"(v));
}
__device__ __forceinline__ u64 fma2(u64 a, u64 b, u64 c) {
    u64 d; asm("fma.rn.f32x2 %0, %1, %2, %3;" : "=l"(d) : "l"(a), "l"(b), "l"(c)); return d;
}
__device__ __forceinline__ u64 mul2(u64 a, u64 b) {
    u64 d; asm("mul.rn.f32x2 %0, %1, %2;" : "=l"(d) : "l"(a), "l"(b)); return d;
}
// pack two f32 -> bf16x2 (hi goes to upper half)
__device__ __forceinline__ unsigned int cvt2bf(float hi, float lo) {
    unsigned int r;
    asm("cvt.rn.satfinite.bf16x2.f32 %0, %1, %2;" : "=r"(r) : "f"(hi), "f"(lo));
    return r;
}
__device__ __forceinline__ float tanh_ap(float z) {
    float t; asm("tanh.approx.f32 %0, %1;" : "=f"(t) : "f"(z)); return t;
}

__device__ __forceinline__ float sigmoidf_fast(float z) {
    return __fdividef(1.0f, 1.0f + __expf(-z));
}
__device__ __forceinline__ float warp_sum(float v) {
#pragma unroll
    for (int o = 16; o > 0; o >>= 1) v += __shfl_down_sync(FULLMASK, v, o);
    return v;
}

// ---------------- L1: init — zero accumulators + convert pw1 -> bf16 ----------------
__global__ void k_init(const float* __restrict__ pw1) {
    int idx = blockIdx.x * blockDim.x + threadIdx.x;
    if (idx < 2048) {
        float2 v = __ldg(reinterpret_cast<const float2*>(pw1) + idx);
        g_pwB[idx] = cvt2bf(v.y, v.x);   // idx = c*32 + kp
    }
    if (blockIdx.x == 0) {
        int t = threadIdx.x;
        if (t < CIN) g_m1[t] = 0.0f;
        if (t < 55)  g_m2[t] = 0.0f;
        if (t < C)   g_gsum[t] = 0.0f;
        if (t == 0) { g_syncA = 0u; g_syncB = 0u; }
    }
}

// ---------------- L2: stats — seg bounds + moments + (last block) BN fold ----------------
__global__ __launch_bounds__(256) void k_stats(
        const float* __restrict__ inp, const int* __restrict__ unq,
        const float* __restrict__ W, const float* __restrict__ gamma,
        const float* __restrict__ beta, const float* __restrict__ dw1,
        int n, int s_count) {
    float a1[CIN];
    float a2[55];
#pragma unroll
    for (int k = 0; k < CIN; k++) a1[k] = 0.0f;
#pragma unroll
    for (int k = 0; k < 55; k++) a2[k] = 0.0f;

    int stride = gridDim.x * blockDim.x;
    for (int i = blockIdx.x * blockDim.x + threadIdx.x; i < n; i += stride) {
        // segment boundaries (unq sorted)
        int cur = __ldg(unq + i);
        if (i == 0) {
            for (int t = 0; t <= cur; t++) g_segstart[t] = 0;
        } else {
            int prev = __ldg(unq + i - 1);
            for (int t = prev + 1; t <= cur; t++) g_segstart[t] = i;
        }
        if (i == n - 1) {
            for (int t = cur + 1; t <= s_count; t++) g_segstart[t] = n;
        }
        // moments
        const float* row = inp + (size_t)i * CIN;
        float v[CIN];
#pragma unroll
        for (int k = 0; k < CIN; k++) v[k] = __ldg(row + k);
        int t = 0;
#pragma unroll
        for (int j = 0; j < CIN; j++) {
            a1[j] += v[j];
#pragma unroll
            for (int k = j; k < CIN; k++) { a2[t] += v[j] * v[k]; t++; }
        }
    }

    int lane = threadIdx.x & 31;
#pragma unroll
    for (int j = 0; j < CIN; j++) {
        float r = warp_sum(a1[j]);
        if (lane == 0) atomicAdd(&g_m1[j], r);
    }
#pragma unroll
    for (int t = 0; t < 55; t++) {
        float r = warp_sum(a2[t]);
        if (lane == 0) atomicAdd(&g_m2[t], r);
    }

    // ---- last-block: BN fold + packed-param staging ----
    __threadfence();
    __shared__ unsigned s_ticket;
    if (threadIdx.x == 0) s_ticket = atomicAdd(&g_syncA, 1u);
    __syncthreads();
    if (s_ticket != gridDim.x - 1) return;

    int c = threadIdx.x;
    if (c < C) {
        float invn = 1.0f / (float)n;
        float wr[CIN];
#pragma unroll
        for (int k = 0; k < CIN; k++) wr[k] = W[c * CIN + k];

        float mu = 0.0f;
#pragma unroll
        for (int k = 0; k < CIN; k++) mu += wr[k] * g_m1[k];
        mu *= invn;

        float ex2 = 0.0f;
        int t = 0;
#pragma unroll
        for (int j = 0; j < CIN; j++) {
#pragma unroll
            for (int k = j; k < CIN; k++) {
                float f = wr[j] * wr[k] * g_m2[t];
                ex2 += (k == j) ? f : 2.0f * f;
                t++;
            }
        }
        ex2 *= invn;
        float var = ex2 - mu * mu;
        float alpha = gamma[c] * rsqrtf(var + EPS);
        g_bias[c] = beta[c] - mu * alpha;
#pragma unroll
        for (int k = 0; k < CIN; k++) g_Wf[c * CIN + k] = alpha * wr[k];
    }
    __syncthreads();
    if (c < 32) {
#pragma unroll
        for (int k = 0; k < CIN; k++)
            g_stage.Wfp[c * CIN + k] = pack2(g_Wf[(2 * c) * CIN + k],
                                             g_Wf[(2 * c + 1) * CIN + k]);
        g_stage.biasp[c] = pack2(g_bias[2 * c], g_bias[2 * c + 1]);
        g_stage.dwp[c]   = pack2(dw1[2 * c], dw1[2 * c + 1]);
    }
}

// ---------------- L3: gpass + (last block) global branch xg ----------------
#define GP_TILE 256
__global__ __launch_bounds__(256) void k_gpass_xg(
        const float* __restrict__ inp,
        const float* __restrict__ dw2, const float* __restrict__ pw2, int n) {
    __shared__ __align__(16) float s_v[GP_TILE * 12];
    __shared__ float s_acc[C];

    int t = threadIdx.x;
    int c = t & 63, g = t >> 6;

    float w[CIN];
#pragma unroll
    for (int k = 0; k < CIN; k++) w[k] = g_Wf[c * CIN + k];
    float b = g_bias[c];
    if (t < C) s_acc[t] = 0.0f;

    float acc = 0.0f;
    for (int base = blockIdx.x * GP_TILE; base < n; base += gridDim.x * GP_TILE) {
        int cnt = n - base; if (cnt > GP_TILE) cnt = GP_TILE;
        __syncthreads();
        for (int i = t; i < cnt * CIN; i += 256) {
            int r = i / CIN, k = i - r * CIN;
            s_v[r * 12 + k] = inp[(size_t)base * CIN + i];
        }
        __syncthreads();
        int p0 = g * 64, p1 = p0 + 64; if (p1 > cnt) p1 = cnt;
        for (int p = p0; p < p1; p++) {
            const float* vr = s_v + p * 12;
            float4 va = *reinterpret_cast<const float4*>(vr);
            float4 vb = *reinterpret_cast<const float4*>(vr + 4);
            float2 vc = *reinterpret_cast<const float2*>(vr + 8);
            float x = b;
            x += w[0] * va.x; x += w[1] * va.y; x += w[2] * va.z; x += w[3] * va.w;
            x += w[4] * vb.x; x += w[5] * vb.y; x += w[6] * vb.z; x += w[7] * vb.w;
            x += w[8] * vc.x; x += w[9] * vc.y;
            acc += fmaxf(x, 0.0f);
        }
    }
    atomicAdd(&s_acc[c], acc);
    __syncthreads();
    if (t < C) atomicAdd(&g_gsum[t], s_acc[t]);

    // ---- last-block: xg = pw2 @ relu(dw2 * mean(x)) ----
    __threadfence();
    __shared__ unsigned s_ticket;
    if (t == 0) s_ticket = atomicAdd(&g_syncB, 1u);
    __syncthreads();
    if (s_ticket != gridDim.x - 1) return;

    __shared__ float tt[C];
    if (t < C) tt[t] = fmaxf(dw2[t] * (g_gsum[t] / (float)n), 0.0f);
    __syncthreads();
    if (t < C) {
        float a = 0.0f;
#pragma unroll
        for (int k = 0; k < C; k++) a += pw2[t * C + k] * tt[k];
        g_stage.xg[t] = a;
    }
}

// ---------------- L4: fused pipeline, bf16 mma.sync phase B ----------------
// dynamic shared layout (bytes):
//   xT   [64][130] f32      @ 0      (33280)  x then xi, transposed [ch][pt]
//   swA  [128 pt][144B]     @ 33280  (18432)  sw bf16, row = point, 64 k + pad
//   pwB  [64 n][144B]       @ 51712  (9216)   pw1 bf16, row = out-ch, 64 k + pad
//   Wfp  [32*10]   u64      @ 60928  (2560)
//   bp   [32]      u64      @ 63488  (256)
//   dwp  [32]      u64      @ 63744  (256)
//   xg   [64]      f32      @ 64000  (256)
//   s_u  [128]     int      @ 64256  (512)
#define XT_S    130
#define SWA_STRIDE_B 144
#define PWB_STRIDE_B 144
#define OFF_SWA 33280
#define OFF_PWB 51712
#define OFF_WFP 60928
#define OFF_BP  63488
#define OFF_DWP 63744
#define OFF_XG  64000
#define OFF_U   64256
#define PIPE_SMEM 64768

__global__ __launch_bounds__(128, 3) void k_pipe(const float* __restrict__ inp,
                                                 const int* __restrict__ unq,
                                                 int n) {
    extern __shared__ __align__(16) char dsm[];
    float* xT   = reinterpret_cast<float*>(dsm);
    unsigned int* swA32 = reinterpret_cast<unsigned int*>(dsm + OFF_SWA);
    unsigned int* pwB32 = reinterpret_cast<unsigned int*>(dsm + OFF_PWB);
    const ulonglong2* Wfp2 = reinterpret_cast<const ulonglong2*>(dsm + OFF_WFP);
    u64*   wfpw = reinterpret_cast<u64*>(dsm + OFF_WFP);
    u64*   bp   = reinterpret_cast<u64*>(dsm + OFF_BP);
    u64*   dwp  = reinterpret_cast<u64*>(dsm + OFF_DWP);
    float* s_xg = reinterpret_cast<float*>(dsm + OFF_XG);
    int*   s_u  = reinterpret_cast<int*>(dsm + OFF_U);

    int li = threadIdx.x;
    int base = blockIdx.x * 128;
    int cnt = n - base; if (cnt > 128) cnt = 128;
    bool havept = li < cnt;

    // ---- early loads: point-row + unq LDGs first, overlapping staging ----
    float vin[CIN];
    int myu = 0;
    if (havept) {
        const float* row = inp + (size_t)(base + li) * CIN;
#pragma unroll
        for (int k = 0; k < CIN; k++) vin[k] = __ldg(row + k);
        myu = __ldg(unq + base + li);
    }

    // staging: pre-converted pw1 bf16 rows (8 KB copy)
    for (int t = li; t < 2048; t += 128) {
        int c = t >> 5, kp = t & 31;
        pwB32[c * 36 + kp] = g_pwB[t];
    }
    for (int t = li; t < 32 * CIN; t += 128) wfpw[t] = g_stage.Wfp[t];
    if (li < 32) { bp[li] = g_stage.biasp[li]; dwp[li] = g_stage.dwp[li]; }
    if (li < C) s_xg[li] = g_stage.xg[li];
    if (havept) s_u[li] = myu;
    __syncthreads();

    // ---- phase A: folded linear + relu + swish (x -> xT, sw -> swA bf16) ----
    if (havept) {
        u64 vd[CIN];
#pragma unroll
        for (int k = 0; k < CIN; k++) vd[k] = pack2(vin[k], vin[k]);
#pragma unroll
        for (int cp = 0; cp < 32; cp++) {
            ulonglong2 wA = Wfp2[cp * 5 + 0];
            ulonglong2 wB = Wfp2[cp * 5 + 1];
            ulonglong2 wC = Wfp2[cp * 5 + 2];
            ulonglong2 wD = Wfp2[cp * 5 + 3];
            ulonglong2 wE = Wfp2[cp * 5 + 4];
            u64 a = bp[cp];
            a = fma2(wA.x, vd[0], a); a = fma2(wA.y, vd[1], a);
            a = fma2(wB.x, vd[2], a); a = fma2(wB.y, vd[3], a);
            a = fma2(wC.x, vd[4], a); a = fma2(wC.y, vd[5], a);
            a = fma2(wD.x, vd[6], a); a = fma2(wD.y, vd[7], a);
            a = fma2(wE.x, vd[8], a); a = fma2(wE.y, vd[9], a);
            float lo, hi; unpack2(a, lo, hi);
            lo = fmaxf(lo, 0.0f); hi = fmaxf(hi, 0.0f);
            xT[(2 * cp) * XT_S + li]     = lo;
            xT[(2 * cp + 1) * XT_S + li] = hi;
            u64 sp = mul2(pack2(lo, hi), dwp[cp]);
            float sa, sb; unpack2(sp, sa, sb);
            // swish(s) = 0.5*s*(1 + tanh(0.5*s))
            float ha = 0.5f * sa, hb = 0.5f * sb;
            float swa = fmaf(ha, tanh_ap(ha), ha);
            float swb = fmaf(hb, tanh_ap(hb), hb);
            swA32[li * 36 + cp] = cvt2bf(swb, swa);   // lo16 = k even, hi16 = k odd
        }
    } else {
#pragma unroll
        for (int c = 0; c < C; c++) xT[c * XT_S + li] = 0.0f;
#pragma unroll
        for (int cp = 0; cp < 32; cp++) swA32[li * 36 + cp] = 0u;
    }
    __syncthreads();

    // ---- phase B: tensor-core GEMM xl[p][c] = sum_k sw[p][k] * pwB[c][k] ----
    {
        int w = li >> 5, lane = li & 31;
        int mbase = w * 32;

        unsigned swA_base = (unsigned)__cvta_generic_to_shared(dsm + OFF_SWA);
        unsigned pwB_base = (unsigned)__cvta_generic_to_shared(dsm + OFF_PWB);

        float acc[2][8][4];
#pragma unroll
        for (int mt = 0; mt < 2; mt++)
#pragma unroll
            for (int j = 0; j < 8; j++)
#pragma unroll
                for (int r = 0; r < 4; r++) acc[mt][j][r] = 0.0f;

#pragma unroll
        for (int t = 0; t < 4; t++) {
            unsigned int a[2][4];
#pragma unroll
            for (int mt = 0; mt < 2; mt++) {
                unsigned addrA = swA_base
                    + (mbase + mt * 16 + (lane & 15)) * SWA_STRIDE_B
                    + (lane >> 4) * 16 + t * 32;
                asm volatile(
                    "ldmatrix.sync.aligned.m8n8.x4.shared.b16 {%0,%1,%2,%3}, [%4];"
                    : "=r"(a[mt][0]), "=r"(a[mt][1]), "=r"(a[mt][2]), "=r"(a[mt][3])
                    : "r"(addrA));
            }
#pragma unroll
            for (int j = 0; j < 8; j++) {
                unsigned int b0, b1;
                unsigned addrB = pwB_base
                    + (8 * j + (lane & 7)) * PWB_STRIDE_B
                    + ((lane >> 3) & 1) * 16 + t * 32;
                asm volatile(
                    "ldmatrix.sync.aligned.m8n8.x2.shared.b16 {%0,%1}, [%2];"
                    : "=r"(b0), "=r"(b1) : "r"(addrB));
#pragma unroll
                for (int mt = 0; mt < 2; mt++) {
                    asm volatile(
                        "mma.sync.aligned.m16n8k16.row.col.f32.bf16.bf16.f32 "
                        "{%0,%1,%2,%3}, {%4,%5,%6,%7}, {%8,%9}, {%0,%1,%2,%3};"
                        : "+f"(acc[mt][j][0]), "+f"(acc[mt][j][1]),
                          "+f"(acc[mt][j][2]), "+f"(acc[mt][j][3])
                        : "r"(a[mt][0]), "r"(a[mt][1]), "r"(a[mt][2]), "r"(a[mt][3]),
                          "r"(b0), "r"(b1));
                }
            }
        }

        // epilogue: wei = sigmoid(xl + xg); xi = x*(1+wei)
        //           1 + wei = 1.5 + 0.5*tanh(0.5*(xl+xg))
#pragma unroll
        for (int mt = 0; mt < 2; mt++) {
            int prow = mbase + mt * 16 + (lane >> 2);
#pragma unroll
            for (int j = 0; j < 8; j++) {
                int c0 = 8 * j + 2 * (lane & 3);
                float xg0 = s_xg[c0], xg1 = s_xg[c0 + 1];
#pragma unroll
                for (int h = 0; h < 2; h++) {
                    int p = prow + 8 * h;
                    float t0 = tanh_ap(0.5f * (acc[mt][j][2 * h]     + xg0));
                    float t1 = tanh_ap(0.5f * (acc[mt][j][2 * h + 1] + xg1));
                    float w0 = fmaf(0.5f, t0, 1.5f);
                    float w1 = fmaf(0.5f, t1, 1.5f);
                    xT[c0 * XT_S + p]       *= w0;
                    xT[(c0 + 1) * XT_S + p] *= w1;
                }
            }
        }
    }
    __syncthreads();

    // ---- phase C: per-pillar partial (max,sum) per 64-pt subtile -> 2-slot scratch ----
    {
        int h = li >> 6, c = li & 63;
        int p = h * 64, pend = p + 64; if (pend > cnt) pend = cnt;
        if (p < pend) {
            int mytile = (base >> 6) + h;
            int cur = s_u[p];
            float v = xT[c * XT_S + p];
            float mx = v, sm = v;
            for (p++; p < pend; p++) {
                int u = s_u[p];
                float w = xT[c * XT_S + p];
                if (u != cur) {
                    size_t slot = ((g_segstart[cur] >> 6) == mytile) ? 0 : 1;
                    size_t idx = slot * ((size_t)SMAX * C) + (size_t)cur * C + c;
                    g_pmax[idx] = mx;
                    g_psum[idx] = sm;
                    cur = u; mx = w; sm = w;
                } else {
                    mx = fmaxf(mx, w); sm += w;
                }
            }
            size_t slot = ((g_segstart[cur] >> 6) == mytile) ? 0 : 1;
            size_t idx = slot * ((size_t)SMAX * C) + (size_t)cur * C + c;
            g_pmax[idx] = mx;
            g_psum[idx] = sm;
        }
    }
}

// ---------------- L5: combine per-pillar partials -> out ----------------
__global__ __launch_bounds__(256) void k_combine(float* __restrict__ out, int s_count) {
    int s = blockIdx.x * 8 + (threadIdx.x >> 5);
    int lane = threadIdx.x & 31;
    if (s >= s_count) return;
    int p0 = g_segstart[s], p1 = g_segstart[s + 1];
    size_t i0 = (size_t)s * C + 2 * lane;
    if (p1 <= p0) {
        out[i0] = 0.0f; out[i0 + 1] = 0.0f;
        return;
    }
    float2 m = *reinterpret_cast<const float2*>(g_pmax + i0);
    float2 q = *reinterpret_cast<const float2*>(g_psum + i0);
    if (((p1 - 1) >> 6) > (p0 >> 6)) {
        size_t i1 = (size_t)SMAX * C + i0;
        float2 m1 = *reinterpret_cast<const float2*>(g_pmax + i1);
        float2 q1 = *reinterpret_cast<const float2*>(g_psum + i1);
        m.x = fmaxf(m.x, m1.x); m.y = fmaxf(m.y, m1.y);
        q.x += q1.x; q.y += q1.y;
    }
    *reinterpret_cast<float2*>(out + i0) = make_float2(m.x + q.x, m.y + q.y);
}

// ---------------- launch ----------------
extern "C" void kernel_launch(void* const* d_in, const int* in_sizes, int n_in,
                              void* d_out, int out_size) {
    const float* inp   = (const float*)d_in[0];
    const int*   unq   = (const int*)d_in[1];
    const float* W     = (const float*)d_in[2];
    const float* gamma = (const float*)d_in[3];
    const float* beta  = (const float*)d_in[4];
    const float* dw1   = (const float*)d_in[5];
    const float* pw1   = (const float*)d_in[6];
    const float* dw2   = (const float*)d_in[7];
    const float* pw2   = (const float*)d_in[8];
    float* out = (float*)d_out;

    int n = in_sizes[0] / CIN;     // 1,000,000
    int s = out_size / C;          // 30,000

    static bool attr_done = false;
    if (!attr_done) {
        cudaFuncSetAttribute(k_pipe, cudaFuncAttributeMaxDynamicSharedMemorySize,
                             PIPE_SMEM);
        attr_done = true;
    }

    k_init<<<8, 256>>>(pw1);                                          // L1
    k_stats<<<592, 256>>>(inp, unq, W, gamma, beta, dw1, n, s);       // L2
    k_gpass_xg<<<592, 256>>>(inp, dw2, pw2, n);                       // L3
    k_pipe<<<(n + 127) / 128, 128, PIPE_SMEM>>>(inp, unq, n);         // L4 (profiled)
    k_combine<<<(s + 7) / 8, 256>>>(out, s);                          // L5
}

// round 17
// speedup vs baseline: 1.1147x; 1.0369x over previous
#include <cuda_runtime.h>
#include <cstdint>

#define CIN  10
#define C    64
#define SMAX 30001
#define EPS  1e-3f
#define FULLMASK 0xffffffffu

typedef unsigned long long u64;

// ---------------- parameter staging (read by k_pipe into shared) ----------------
struct Params {
    u64   Wfp[32 * CIN];   // BN-folded linear weights, channel-pair packed
    u64   biasp[32];
    u64   dwp[32];
    float xg[C];
};
__device__ Params g_stage;

// ---------------- device scratch ----------------
__device__ float g_m1[CIN];
__device__ float g_m2[55];
__device__ float g_Wf[C * CIN];
__device__ float g_bias[C];
__device__ float g_gsum[C];
__device__ int   g_segstart[SMAX];
__device__ unsigned g_syncA;     // last-block tickets
__device__ unsigned g_syncB;
__device__ unsigned g_pwB[2048]; // pw1 as bf16x2, [c][kp] (kp = k/2)
// per-pillar partials, 3 slots (32-pt groups; 34-pt pillars span <= 3 groups)
__device__ float g_pmax[(size_t)3 * SMAX * C];
__device__ float g_psum[(size_t)3 * SMAX * C];

// ---------------- packed f32x2 / bf16 helpers ----------------
__device__ __forceinline__ u64 pack2(float lo, float hi) {
    u64 r; asm("mov.b64 %0, {%1, %2};" : "=l"(r) : "f"(lo), "f"(hi)); return r;
}
__device__ __forceinline__ void unpack2(u64 v, float& lo, float& hi) {
    asm("mov.b64 {%0, %1}, %2;" : "=f"(lo), "=f"(hi) : "l"(v));
}
__device__ __forceinline__ u64 fma2(u64 a, u64 b, u64 c) {
    u64 d; asm("fma.rn.f32x2 %0, %1, %2, %3;" : "=l"(d) : "l"(a), "l"(b), "l"(c)); return d;
}
__device__ __forceinline__ u64 mul2(u64 a, u64 b) {
    u64 d; asm("mul.rn.f32x2 %0, %1, %2;" : "=l"(d) : "l"(a), "l"(b)); return d;
}
// pack two f32 -> bf16x2 (hi goes to upper half)
__device__ __forceinline__ unsigned int cvt2bf(float hi, float lo) {
    unsigned int r;
    asm("cvt.rn.satfinite.bf16x2.f32 %0, %1, %2;" : "=r"(r) : "f"(hi), "f"(lo));
    return r;
}
__device__ __forceinline__ float bf_lo(unsigned int w) {
    return __uint_as_float(w << 16);
}
__device__ __forceinline__ float bf_hi(unsigned int w) {
    return __uint_as_float(w & 0xffff0000u);
}
__device__ __forceinline__ float tanh_ap(float z) {
    float t; asm("tanh.approx.f32 %0, %1;" : "=f"(t) : "f"(z)); return t;
}
__device__ __forceinline__ float warp_sum(float v) {
#pragma unroll
    for (int o = 16; o > 0; o >>= 1) v += __shfl_down_sync(FULLMASK, v, o);
    return v;
}

// ---------------- L1: init — zero accumulators + convert pw1 -> bf16 ----------------
__global__ void k_init(const float* __restrict__ pw1) {
    int idx = blockIdx.x * blockDim.x + threadIdx.x;
    if (idx < 2048) {
        float2 v = __ldg(reinterpret_cast<const float2*>(pw1) + idx);
        g_pwB[idx] = cvt2bf(v.y, v.x);   // idx = c*32 + kp
    }
    if (blockIdx.x == 0) {
        int t = threadIdx.x;
        if (t < CIN) g_m1[t] = 0.0f;
        if (t < 55)  g_m2[t] = 0.0f;
        if (t < C)   g_gsum[t] = 0.0f;
        if (t == 0) { g_syncA = 0u; g_syncB = 0u; }
    }
}

// ---------------- L2: stats — seg bounds + moments + (last block) BN fold ----------------
__global__ __launch_bounds__(256) void k_stats(
        const float* __restrict__ inp, const int* __restrict__ unq,
        const float* __restrict__ W, const float* __restrict__ gamma,
        const float* __restrict__ beta, const float* __restrict__ dw1,
        int n, int s_count) {
    float a1[CIN];
    float a2[55];
#pragma unroll
    for (int k = 0; k < CIN; k++) a1[k] = 0.0f;
#pragma unroll
    for (int k = 0; k < 55; k++) a2[k] = 0.0f;

    int stride = gridDim.x * blockDim.x;
    for (int i = blockIdx.x * blockDim.x + threadIdx.x; i < n; i += stride) {
        int cur = __ldg(unq + i);
        if (i == 0) {
            for (int t = 0; t <= cur; t++) g_segstart[t] = 0;
        } else {
            int prev = __ldg(unq + i - 1);
            for (int t = prev + 1; t <= cur; t++) g_segstart[t] = i;
        }
        if (i == n - 1) {
            for (int t = cur + 1; t <= s_count; t++) g_segstart[t] = n;
        }
        const float* row = inp + (size_t)i * CIN;
        float v[CIN];
#pragma unroll
        for (int k = 0; k < CIN; k++) v[k] = __ldg(row + k);
        int t = 0;
#pragma unroll
        for (int j = 0; j < CIN; j++) {
            a1[j] += v[j];
#pragma unroll
            for (int k = j; k < CIN; k++) { a2[t] += v[j] * v[k]; t++; }
        }
    }

    int lane = threadIdx.x & 31;
#pragma unroll
    for (int j = 0; j < CIN; j++) {
        float r = warp_sum(a1[j]);
        if (lane == 0) atomicAdd(&g_m1[j], r);
    }
#pragma unroll
    for (int t = 0; t < 55; t++) {
        float r = warp_sum(a2[t]);
        if (lane == 0) atomicAdd(&g_m2[t], r);
    }

    // ---- last-block: BN fold + packed-param staging ----
    __threadfence();
    __shared__ unsigned s_ticket;
    if (threadIdx.x == 0) s_ticket = atomicAdd(&g_syncA, 1u);
    __syncthreads();
    if (s_ticket != gridDim.x - 1) return;

    int c = threadIdx.x;
    if (c < C) {
        float invn = 1.0f / (float)n;
        float wr[CIN];
#pragma unroll
        for (int k = 0; k < CIN; k++) wr[k] = W[c * CIN + k];

        float mu = 0.0f;
#pragma unroll
        for (int k = 0; k < CIN; k++) mu += wr[k] * g_m1[k];
        mu *= invn;

        float ex2 = 0.0f;
        int t = 0;
#pragma unroll
        for (int j = 0; j < CIN; j++) {
#pragma unroll
            for (int k = j; k < CIN; k++) {
                float f = wr[j] * wr[k] * g_m2[t];
                ex2 += (k == j) ? f : 2.0f * f;
                t++;
            }
        }
        ex2 *= invn;
        float var = ex2 - mu * mu;
        float alpha = gamma[c] * rsqrtf(var + EPS);
        g_bias[c] = beta[c] - mu * alpha;
#pragma unroll
        for (int k = 0; k < CIN; k++) g_Wf[c * CIN + k] = alpha * wr[k];
    }
    __syncthreads();
    if (c < 32) {
#pragma unroll
        for (int k = 0; k < CIN; k++)
            g_stage.Wfp[c * CIN + k] = pack2(g_Wf[(2 * c) * CIN + k],
                                             g_Wf[(2 * c + 1) * CIN + k]);
        g_stage.biasp[c] = pack2(g_bias[2 * c], g_bias[2 * c + 1]);
        g_stage.dwp[c]   = pack2(dw1[2 * c], dw1[2 * c + 1]);
    }
}

// ---------------- L3: gpass + (last block) global branch xg ----------------
#define GP_TILE 256
__global__ __launch_bounds__(256) void k_gpass_xg(
        const float* __restrict__ inp,
        const float* __restrict__ dw2, const float* __restrict__ pw2, int n) {
    __shared__ __align__(16) float s_v[GP_TILE * 12];
    __shared__ float s_acc[C];

    int t = threadIdx.x;
    int c = t & 63, g = t >> 6;

    float w[CIN];
#pragma unroll
    for (int k = 0; k < CIN; k++) w[k] = g_Wf[c * CIN + k];
    float b = g_bias[c];
    if (t < C) s_acc[t] = 0.0f;

    float acc = 0.0f;
    for (int base = blockIdx.x * GP_TILE; base < n; base += gridDim.x * GP_TILE) {
        int cnt = n - base; if (cnt > GP_TILE) cnt = GP_TILE;
        __syncthreads();
        for (int i = t; i < cnt * CIN; i += 256) {
            int r = i / CIN, k = i - r * CIN;
            s_v[r * 12 + k] = inp[(size_t)base * CIN + i];
        }
        __syncthreads();
        int p0 = g * 64, p1 = p0 + 64; if (p1 > cnt) p1 = cnt;
        for (int p = p0; p < p1; p++) {
            const float* vr = s_v + p * 12;
            float4 va = *reinterpret_cast<const float4*>(vr);
            float4 vb = *reinterpret_cast<const float4*>(vr + 4);
            float2 vc = *reinterpret_cast<const float2*>(vr + 8);
            float x = b;
            x += w[0] * va.x; x += w[1] * va.y; x += w[2] * va.z; x += w[3] * va.w;
            x += w[4] * vb.x; x += w[5] * vb.y; x += w[6] * vb.z; x += w[7] * vb.w;
            x += w[8] * vc.x; x += w[9] * vc.y;
            acc += fmaxf(x, 0.0f);
        }
    }
    atomicAdd(&s_acc[c], acc);
    __syncthreads();
    if (t < C) atomicAdd(&g_gsum[t], s_acc[t]);

    // ---- last-block: xg = pw2 @ relu(dw2 * mean(x)) ----
    __threadfence();
    __shared__ unsigned s_ticket;
    if (t == 0) s_ticket = atomicAdd(&g_syncB, 1u);
    __syncthreads();
    if (s_ticket != gridDim.x - 1) return;

    __shared__ float tt[C];
    if (t < C) tt[t] = fmaxf(dw2[t] * (g_gsum[t] / (float)n), 0.0f);
    __syncthreads();
    if (t < C) {
        float a = 0.0f;
#pragma unroll
        for (int k = 0; k < C; k++) a += pw2[t * C + k] * tt[k];
        g_stage.xg[t] = a;
    }
}

// ---------------- L4: fused pipeline, bf16 mma.sync phase B ----------------
// dynamic shared layout (bytes):
//   xP   [128 pt][37 u32]   @ 0      (18944)  xi bf16x2 channel pairs, stride 148B
//   swA  [128 pt][144B]     @ 18944  (18432)  sw bf16, unit-swizzled rows
//   pwB  [64 n][144B]       @ 37376  (9216)   pw1 bf16, row = out-ch
//   Wfp  [32*10]   u64      @ 46592  (2560)
//   bp   [32]      u64      @ 49152  (256)
//   dwp  [32]      u64      @ 49408  (256)
//   xg   [64]      f32      @ 49664  (256)
//   s_u  [128]     int      @ 49920  (512)
#define XP_S    37
#define SWA_STRIDE_B 144
#define PWB_STRIDE_B 144
#define OFF_SWA 18944
#define OFF_PWB 37376
#define OFF_WFP 46592
#define OFF_BP  49152
#define OFF_DWP 49408
#define OFF_XG  49664
#define OFF_U   49920
#define PIPE_SMEM 50432

__global__ __launch_bounds__(128, 4) void k_pipe(const float* __restrict__ inp,
                                                 const int* __restrict__ unq,
                                                 int n) {
    extern __shared__ __align__(16) char dsm[];
    unsigned int* xP32  = reinterpret_cast<unsigned int*>(dsm);
    unsigned int* swA32 = reinterpret_cast<unsigned int*>(dsm + OFF_SWA);
    unsigned int* pwB32 = reinterpret_cast<unsigned int*>(dsm + OFF_PWB);
    const ulonglong2* Wfp2 = reinterpret_cast<const ulonglong2*>(dsm + OFF_WFP);
    u64*   wfpw = reinterpret_cast<u64*>(dsm + OFF_WFP);
    u64*   bp   = reinterpret_cast<u64*>(dsm + OFF_BP);
    u64*   dwp  = reinterpret_cast<u64*>(dsm + OFF_DWP);
    float* s_xg = reinterpret_cast<float*>(dsm + OFF_XG);
    int*   s_u  = reinterpret_cast<int*>(dsm + OFF_U);

    int li = threadIdx.x;
    int base = blockIdx.x * 128;
    int cnt = n - base; if (cnt > 128) cnt = 128;
    bool havept = li < cnt;

    // ---- early loads: point-row + unq LDGs first, overlapping staging ----
    float vin[CIN];
    int myu = 0;
    if (havept) {
        const float* row = inp + (size_t)(base + li) * CIN;
#pragma unroll
        for (int k = 0; k < CIN; k++) vin[k] = __ldg(row + k);
        myu = __ldg(unq + base + li);
    }

    // staging: pre-converted pw1 bf16 rows (8 KB copy, coalesced per warp)
    for (int t = li; t < 2048; t += 128) {
        int c = t >> 5, kp = t & 31;
        pwB32[c * 36 + kp] = g_pwB[t];
    }
    for (int t = li; t < 32 * CIN; t += 128) wfpw[t] = g_stage.Wfp[t];
    if (li < 32) { bp[li] = g_stage.biasp[li]; dwp[li] = g_stage.dwp[li]; }
    if (li < C) s_xg[li] = g_stage.xg[li];
    if (havept) s_u[li] = myu;
    __syncthreads();

    // ---- phase A: folded linear + relu + swish (x -> xP bf16, sw -> swA bf16 swizzled) ----
    if (havept) {
        u64 vd[CIN];
#pragma unroll
        for (int k = 0; k < CIN; k++) vd[k] = pack2(vin[k], vin[k]);
        int swz = 4 * (li & 1);   // unit swizzle for this row
#pragma unroll
        for (int cp = 0; cp < 32; cp++) {
            ulonglong2 wA = Wfp2[cp * 5 + 0];
            ulonglong2 wB = Wfp2[cp * 5 + 1];
            ulonglong2 wC = Wfp2[cp * 5 + 2];
            ulonglong2 wD = Wfp2[cp * 5 + 3];
            ulonglong2 wE = Wfp2[cp * 5 + 4];
            u64 a = bp[cp];
            a = fma2(wA.x, vd[0], a); a = fma2(wA.y, vd[1], a);
            a = fma2(wB.x, vd[2], a); a = fma2(wB.y, vd[3], a);
            a = fma2(wC.x, vd[4], a); a = fma2(wC.y, vd[5], a);
            a = fma2(wD.x, vd[6], a); a = fma2(wD.y, vd[7], a);
            a = fma2(wE.x, vd[8], a); a = fma2(wE.y, vd[9], a);
            float lo, hi; unpack2(a, lo, hi);
            lo = fmaxf(lo, 0.0f); hi = fmaxf(hi, 0.0f);
            xP32[li * XP_S + cp] = cvt2bf(hi, lo);   // lo16 = ch 2cp
            u64 sp = mul2(pack2(lo, hi), dwp[cp]);
            float sa, sb; unpack2(sp, sa, sb);
            // swish(s) = 0.5*s*(1 + tanh(0.5*s))
            float ha = 0.5f * sa, hb = 0.5f * sb;
            float swa = fmaf(ha, tanh_ap(ha), ha);
            float swb = fmaf(hb, tanh_ap(hb), hb);
            int up = ((cp >> 2) + swz) & 7;          // swizzled 16B-unit
            swA32[li * 36 + up * 4 + (cp & 3)] = cvt2bf(swb, swa);
        }
    } else {
#pragma unroll
        for (int cp = 0; cp < 32; cp++) xP32[li * XP_S + cp] = 0u;
#pragma unroll
        for (int t = 0; t < 36; t++) swA32[li * 36 + t] = 0u;
    }
    __syncthreads();

    // ---- phase B: tensor-core GEMM xl[p][c] = sum_k sw[p][k] * pwB[c][k] ----
    {
        int w = li >> 5, lane = li & 31;
        int mbase = w * 32;

        unsigned swA_base = (unsigned)__cvta_generic_to_shared(dsm + OFF_SWA);
        unsigned pwB_base = (unsigned)__cvta_generic_to_shared(dsm + OFF_PWB);

        float acc[2][8][4];
#pragma unroll
        for (int mt = 0; mt < 2; mt++)
#pragma unroll
            for (int j = 0; j < 8; j++)
#pragma unroll
                for (int r = 0; r < 4; r++) acc[mt][j][r] = 0.0f;

#pragma unroll
        for (int t = 0; t < 4; t++) {
            unsigned int a[2][4];
#pragma unroll
            for (int mt = 0; mt < 2; mt++) {
                int rowA = mbase + mt * 16 + (lane & 15);
                int unitA = ((2 * t + (lane >> 4)) + 4 * (rowA & 1)) & 7;  // same swizzle
                unsigned addrA = swA_base + rowA * SWA_STRIDE_B + unitA * 16;
                asm volatile(
                    "ldmatrix.sync.aligned.m8n8.x4.shared.b16 {%0,%1,%2,%3}, [%4];"
                    : "=r"(a[mt][0]), "=r"(a[mt][1]), "=r"(a[mt][2]), "=r"(a[mt][3])
                    : "r"(addrA));
            }
#pragma unroll
            for (int j = 0; j < 8; j++) {
                unsigned int b0, b1;
                unsigned addrB = pwB_base
                    + (8 * j + (lane & 7)) * PWB_STRIDE_B
                    + ((lane >> 3) & 1) * 16 + t * 32;
                asm volatile(
                    "ldmatrix.sync.aligned.m8n8.x2.shared.b16 {%0,%1}, [%2];"
                    : "=r"(b0), "=r"(b1) : "r"(addrB));
#pragma unroll
                for (int mt = 0; mt < 2; mt++) {
                    asm volatile(
                        "mma.sync.aligned.m16n8k16.row.col.f32.bf16.bf16.f32 "
                        "{%0,%1,%2,%3}, {%4,%5,%6,%7}, {%8,%9}, {%0,%1,%2,%3};"
                        : "+f"(acc[mt][j][0]), "+f"(acc[mt][j][1]),
                          "+f"(acc[mt][j][2]), "+f"(acc[mt][j][3])
                        : "r"(a[mt][0]), "r"(a[mt][1]), "r"(a[mt][2]), "r"(a[mt][3]),
                          "r"(b0), "r"(b1));
                }
            }
        }

        // epilogue: 1 + wei = 1.5 + 0.5*tanh(0.5*(xl+xg)); xi = x*(1+wei) RMW on xP
#pragma unroll
        for (int mt = 0; mt < 2; mt++) {
            int prow = mbase + mt * 16 + (lane >> 2);
#pragma unroll
            for (int j = 0; j < 8; j++) {
                int c0 = 8 * j + 2 * (lane & 3);
                int cp2 = 4 * j + (lane & 3);
                float xg0 = s_xg[c0], xg1 = s_xg[c0 + 1];
#pragma unroll
                for (int h = 0; h < 2; h++) {
                    int p = prow + 8 * h;
                    float t0 = tanh_ap(0.5f * (acc[mt][j][2 * h]     + xg0));
                    float t1 = tanh_ap(0.5f * (acc[mt][j][2 * h + 1] + xg1));
                    float w0 = fmaf(0.5f, t0, 1.5f);
                    float w1 = fmaf(0.5f, t1, 1.5f);
                    unsigned int xw = xP32[p * XP_S + cp2];
                    xP32[p * XP_S + cp2] = cvt2bf(bf_hi(xw) * w1, bf_lo(xw) * w0);
                }
            }
        }
    }
    __syncthreads();

    // ---- phase C: per-pillar partial (max,sum) per 32-pt group -> 3-slot scratch ----
    {
        int cp = li & 31, g = li >> 5;
        int p = g * 32, pend = p + 32; if (pend > cnt) pend = cnt;
        if (p < pend) {
            int mygroup = (base >> 5) + g;
            int cur = s_u[p];
            unsigned int xw = xP32[p * XP_S + cp];
            float mx0 = bf_lo(xw), sm0 = mx0;
            float mx1 = bf_hi(xw), sm1 = mx1;
            for (p++; p < pend; p++) {
                int u = s_u[p];
                xw = xP32[p * XP_S + cp];
                float w0 = bf_lo(xw), w1 = bf_hi(xw);
                if (u != cur) {
                    int slot = mygroup - (g_segstart[cur] >> 5);
                    size_t idx = (size_t)slot * ((size_t)SMAX * C)
                               + (size_t)cur * C + 2 * cp;
                    *reinterpret_cast<float2*>(g_pmax + idx) = make_float2(mx0, mx1);
                    *reinterpret_cast<float2*>(g_psum + idx) = make_float2(sm0, sm1);
                    cur = u; mx0 = w0; sm0 = w0; mx1 = w1; sm1 = w1;
                } else {
                    mx0 = fmaxf(mx0, w0); sm0 += w0;
                    mx1 = fmaxf(mx1, w1); sm1 += w1;
                }
            }
            int slot = mygroup - (g_segstart[cur] >> 5);
            size_t idx = (size_t)slot * ((size_t)SMAX * C) + (size_t)cur * C + 2 * cp;
            *reinterpret_cast<float2*>(g_pmax + idx) = make_float2(mx0, mx1);
            *reinterpret_cast<float2*>(g_psum + idx) = make_float2(sm0, sm1);
        }
    }
}

// ---------------- L5: combine per-pillar partials (up to 3 slots) -> out ----------------
__global__ __launch_bounds__(256) void k_combine(float* __restrict__ out, int s_count) {
    int s = blockIdx.x * 8 + (threadIdx.x >> 5);
    int lane = threadIdx.x & 31;
    if (s >= s_count) return;
    int p0 = g_segstart[s], p1 = g_segstart[s + 1];
    size_t i0 = (size_t)s * C + 2 * lane;
    if (p1 <= p0) {
        out[i0] = 0.0f; out[i0 + 1] = 0.0f;
        return;
    }
    int span = ((p1 - 1) >> 5) - (p0 >> 5);   // 0..2
    float2 m = *reinterpret_cast<const float2*>(g_pmax + i0);
    float2 q = *reinterpret_cast<const float2*>(g_psum + i0);
    if (span >= 1) {
        size_t i1 = (size_t)SMAX * C + i0;
        float2 m1 = *reinterpret_cast<const float2*>(g_pmax + i1);
        float2 q1 = *reinterpret_cast<const float2*>(g_psum + i1);
        m.x = fmaxf(m.x, m1.x); m.y = fmaxf(m.y, m1.y);
        q.x += q1.x; q.y += q1.y;
    }
    if (span >= 2) {
        size_t i2 = 2 * ((size_t)SMAX * C) + i0;
        float2 m2 = *reinterpret_cast<const float2*>(g_pmax + i2);
        float2 q2 = *reinterpret_cast<const float2*>(g_psum + i2);
        m.x = fmaxf(m.x, m2.x); m.y = fmaxf(m.y, m2.y);
        q.x += q2.x; q.y += q2.y;
    }
    *reinterpret_cast<float2*>(out + i0) = make_float2(m.x + q.x, m.y + q.y);
}

// ---------------- launch ----------------
extern "C" void kernel_launch(void* const* d_in, const int* in_sizes, int n_in,
                              void* d_out, int out_size) {
    const float* inp   = (const float*)d_in[0];
    const int*   unq   = (const int*)d_in[1];
    const float* W     = (const float*)d_in[2];
    const float* gamma = (const float*)d_in[3];
    const float* beta  = (const float*)d_in[4];
    const float* dw1   = (const float*)d_in[5];
    const float* pw1   = (const float*)d_in[6];
    const float* dw2   = (const float*)d_in[7];
    const float* pw2   = (const float*)d_in[8];
    float* out = (float*)d_out;

    int n = in_sizes[0] / CIN;     // 1,000,000
    int s = out_size / C;          // 30,000

    static bool attr_done = false;
    if (!attr_done) {
        cudaFuncSetAttribute(k_pipe, cudaFuncAttributeMaxDynamicSharedMemorySize,
                             PIPE_SMEM);
        attr_done = true;
    }

    k_init<<<8, 256>>>(pw1);                                          // L1
    k_stats<<<592, 256>>>(inp, unq, W, gamma, beta, dw1, n, s);       // L2
    k_gpass_xg<<<592, 256>>>(inp, dw2, pw2, n);                       // L3
    k_pipe<<<(n + 127) / 128, 128, PIPE_SMEM>>>(inp, unq, n);         // L4 (profiled)
    k_combine<<<(s + 7) / 8, 256>>>(out, s);                          // L5
}